// round 4
// baseline (speedup 1.0000x reference)
#include <cuda_runtime.h>
#include <cuda_bf16.h>
#include <math.h>
#include <float.h>
#include <stdint.h>

#define BSZ   256
#define MROW  32768
#define DIM   512
#define KNEG  10
#define MARGIN_F 0.1f
#define EPS_F 1e-6f
#define TMARGIN_F 0.31622776601683794f

#define BN 64             // j rows per CTA
#define BKC 64            // K per chunk (bf16)
#define NCHUNK (DIM / BKC)  // 8
#define PADK 72           // padded k-stride in bf16 elems (144 B); ldsm banks 4r mod 32 -> conflict-free
#define STRB (PADK * 2)   // 144 bytes

// dynamic smem layout (bytes)
#define A_T0   0
#define A_T1   36864           // 256*144
#define B_T0   73728
#define B_T1   82944           // + 64*144
#define NN_OFF 92160           // 64*8 u32 = 2048
#define NNEG_OFF 94208         // 256*10 int = 10240
#define TROW_OFF 104448        // 64 int
#define SMEM_DYN 104704
// epilogue tables overlay the A0 buffer
#define T_TH  0
#define T_NA  1024
#define T_SA  2048
#define T_DAP 3072
#define T_NB  4096
#define T_SB  4352

// ---------------- scratch globals ----------------
__device__ float         g_thresh[BSZ];
__device__ float         g_na[BSZ];
__device__ float         g_sa[BSZ];
__device__ float         g_dap[BSZ];
__device__ int           g_nneg[BSZ * KNEG];
__device__ __align__(256) __nv_bfloat16 g_Abf[BSZ * DIM];
__device__ double        g_total;
__device__ int           g_count;
__device__ unsigned      g_done = 0;

// ---------------- helpers ----------------
__device__ __forceinline__ uint32_t smem_u32(const void* p) {
    uint32_t a;
    asm("{ .reg .u64 t; cvta.to.shared.u64 t, %1; cvt.u32.u64 %0, t; }" : "=r"(a) : "l"(p));
    return a;
}
__device__ __forceinline__ void ldsm_x4(uint32_t* r, uint32_t addr) {
    asm volatile("ldmatrix.sync.aligned.m8n8.x4.shared.b16 {%0,%1,%2,%3}, [%4];"
                 : "=r"(r[0]), "=r"(r[1]), "=r"(r[2]), "=r"(r[3]) : "r"(addr));
}
__device__ __forceinline__ void mma16816(float* d, const uint32_t* a, uint32_t b0, uint32_t b1) {
    asm volatile(
        "mma.sync.aligned.m16n8k16.row.col.f32.bf16.bf16.f32 "
        "{%0,%1,%2,%3}, {%4,%5,%6,%7}, {%8,%9}, {%0,%1,%2,%3};"
        : "+f"(d[0]), "+f"(d[1]), "+f"(d[2]), "+f"(d[3])
        : "r"(a[0]), "r"(a[1]), "r"(a[2]), "r"(a[3]), "r"(b0), "r"(b1));
}
#define CP_ASYNC16(dst, src) \
    asm volatile("cp.async.cg.shared.global [%0], [%1], 16;" :: "r"(dst), "l"(src))
#define CP_COMMIT()  asm volatile("cp.async.commit_group;" ::: "memory")
#define CP_WAIT0()   asm volatile("cp.async.wait_group 0;" ::: "memory")

__inline__ __device__ float warpReduceSum(float v) {
    #pragma unroll
    for (int o = 16; o > 0; o >>= 1) v += __shfl_down_sync(0xffffffffu, v, o);
    return v;
}
__inline__ __device__ int warpReduceSumI(int v) {
    #pragma unroll
    for (int o = 16; o > 0; o >>= 1) v += __shfl_down_sync(0xffffffffu, v, o);
    return v;
}
__device__ __forceinline__ uint32_t packbf(float x, float y) {
    __nv_bfloat162 t = __float22bfloat162_rn(make_float2(x, y));
    return *(uint32_t*)&t;
}

// ---------------- Kernel A: per-query setup + A bf16 conversion ----------------
__global__ void setup_kernel(const float* __restrict__ col,
                             const float* __restrict__ row,
                             const int* __restrict__ targets_col,
                             const int* __restrict__ qidxs,
                             const int* __restrict__ nnegs) {
    int i = blockIdx.x;
    int tid = threadIdx.x;
    const float* q = col + (size_t)i * DIM;
    const float* p = row + (size_t)(BSZ + i) * DIM;

    float na = 0.f, sa = 0.f, ps = 0.f, dap2 = 0.f;
    for (int k = tid; k < DIM; k += blockDim.x) {
        float qv = q[k], pv = p[k];
        na += qv * qv;
        sa += qv;
        ps += qv * pv;
        float dlt = qv - pv + EPS_F;
        dap2 += dlt * dlt;
        g_Abf[i * DIM + k] = __float2bfloat16_rn(qv);
    }
    __shared__ float sh[4][4];
    int w = tid >> 5, l = tid & 31;
    na = warpReduceSum(na); sa = warpReduceSum(sa);
    ps = warpReduceSum(ps); dap2 = warpReduceSum(dap2);
    if (l == 0) { sh[0][w] = na; sh[1][w] = sa; sh[2][w] = ps; sh[3][w] = dap2; }
    __syncthreads();
    if (tid == 0) {
        na = 0.f; sa = 0.f; ps = 0.f; dap2 = 0.f;
        for (int k = 0; k < 4; k++) { na += sh[0][k]; sa += sh[1][k]; ps += sh[2][k]; dap2 += sh[3][k]; }
        int tc = targets_col[i];
        int qloc = 0, has = 0;
        for (int j = 0; j < BSZ; j++) if (qidxs[j] == tc) { qloc = j; has = 1; break; }
        g_thresh[i] = has ? (ps - MARGIN_F) : FLT_MAX;
        g_na[i] = na; g_sa[i] = sa; g_dap[i] = sqrtf(dap2);
        for (int k = 0; k < KNEG; k++) g_nneg[i * KNEG + k] = nnegs[qloc * KNEG + k];
        if (i == 0) { g_total = 0.0; g_count = 0; }
    }
}

// ---------------- Kernel B: gemm + mask + epilogue + finalize ----------------
__global__ __launch_bounds__(512)
void gemm_kernel(const float* __restrict__ Brow,
                 const int* __restrict__ targets_row,
                 float* __restrict__ out, unsigned nblocks) {
    extern __shared__ char dsm[];
    __shared__ float red_s[16];
    __shared__ int   red_c[16];

    uint32_t sb = smem_u32(dsm);
    int tid = threadIdx.x;
    int wid = tid >> 5, lid = tid & 31;
    int j0 = blockIdx.x * BN;

    // loader mapping: B -> row = tid>>3 (0..63), colgrp = tid&7 (x8 floats)
    int brow = tid >> 3;
    int bcg  = tid & 7;

    // warp tiling: 8 (i) x 2 (j); warp tile 32x32
    int i0w = (wid >> 1) * 32, j0w = (wid & 1) * 32;

    float acc[2][4][4];
    #pragma unroll
    for (int a = 0; a < 2; a++)
        #pragma unroll
        for (int b = 0; b < 4; b++)
            #pragma unroll
            for (int c = 0; c < 4; c++) acc[a][b][c] = 0.f;

    float nbacc = 0.f, sbacc = 0.f;

    uint32_t a_lane = (uint32_t)((lid & 15) * STRB + (lid >> 4) * 16);
    uint32_t b_lane = (uint32_t)(((lid & 7) + ((lid >> 4) & 1) * 8) * STRB + ((lid >> 3) & 1) * 16);

    int*      s_nneg = (int*)(dsm + NNEG_OFF);
    int*      s_trow = (int*)(dsm + TROW_OFF);
    unsigned* s_nn   = (unsigned*)(dsm + NN_OFF);

    const float* Bg = Brow + (size_t)(j0 + brow) * DIM + bcg * 8;

    // ---- prologue ----
    {
        // stage nneg table + target rows
        #pragma unroll
        for (int p = 0; p < 5; p++) s_nneg[tid + p * 512] = g_nneg[tid + p * 512];
        if (tid < BN) s_trow[tid] = targets_row[j0 + tid];

        // chunk 0 A via cp.async
        #pragma unroll
        for (int p = 0; p < 4; p++) {
            int g = tid + p * 512;
            int row = g >> 3, h = g & 7;
            CP_ASYNC16(sb + A_T0 + row * STRB + h * 16,
                       (const char*)(g_Abf + row * DIM + h * 8));
        }
        CP_COMMIT();
        float4 b0 = *(const float4*)(Bg + 0);
        float4 b1 = *(const float4*)(Bg + 4);
        __syncthreads();   // staging visible

        // mask compute: warp handles 8 groups x 4 rows
        {
            int i = 0;
            int myneg[KNEG];
            #pragma unroll 1
            for (int g = 0; g < 8; g++) {
                i = g * 32 + lid;
                #pragma unroll
                for (int k = 0; k < KNEG; k++) myneg[k] = s_nneg[i * KNEG + k];
                #pragma unroll
                for (int r = 0; r < 4; r++) {
                    int row = wid * 4 + r;
                    int t = s_trow[row];
                    bool m = false;
                    #pragma unroll
                    for (int k = 0; k < KNEG; k++) m = m || (myneg[k] == t);
                    unsigned word = __ballot_sync(0xffffffffu, m);
                    if (lid == 0) s_nn[row * 8 + g] = word;
                }
            }
        }

        nbacc += b0.x*b0.x + b0.y*b0.y + b0.z*b0.z + b0.w*b0.w
               + b1.x*b1.x + b1.y*b1.y + b1.z*b1.z + b1.w*b1.w;
        sbacc += b0.x + b0.y + b0.z + b0.w + b1.x + b1.y + b1.z + b1.w;
        uint4 pk;
        pk.x = packbf(b0.x, b0.y); pk.y = packbf(b0.z, b0.w);
        pk.z = packbf(b1.x, b1.y); pk.w = packbf(b1.z, b1.w);
        *(uint4*)(dsm + B_T0 + brow * STRB + bcg * 16) = pk;
        CP_WAIT0();
        __syncthreads();
    }

    // ---- mainloop ----
    #pragma unroll 1
    for (int kt = 0; kt < NCHUNK; kt++) {
        int buf = kt & 1;
        uint32_t Ab = sb + (buf ? A_T1 : A_T0);
        uint32_t Bb = sb + (buf ? B_T1 : B_T0);
        uint32_t AbN = sb + (buf ? A_T0 : A_T1);
        char*    BbN = dsm + (buf ? B_T0 : B_T1);

        float4 b0, b1;
        if (kt < NCHUNK - 1) {
            int kc = (kt + 1) * BKC;
            #pragma unroll
            for (int p = 0; p < 4; p++) {
                int g = tid + p * 512;
                int row = g >> 3, h = g & 7;
                CP_ASYNC16(AbN + row * STRB + h * 16,
                           (const char*)(g_Abf + row * DIM + kc + h * 8));
            }
            CP_COMMIT();
            b0 = *(const float4*)(Bg + kc);
            b1 = *(const float4*)(Bg + kc + 4);
        }

        #pragma unroll
        for (int ks = 0; ks < BKC; ks += 16) {
            uint32_t afr[2][4], bfr[2][4];
            #pragma unroll
            for (int mt = 0; mt < 2; mt++)
                ldsm_x4(afr[mt], Ab + (uint32_t)((i0w + mt * 16) * STRB + ks * 2) + a_lane);
            #pragma unroll
            for (int np = 0; np < 2; np++)
                ldsm_x4(bfr[np], Bb + (uint32_t)((j0w + np * 16) * STRB + ks * 2) + b_lane);
            #pragma unroll
            for (int mt = 0; mt < 2; mt++) {
                #pragma unroll
                for (int np = 0; np < 2; np++) {
                    mma16816(acc[mt][np * 2 + 0], afr[mt], bfr[np][0], bfr[np][1]);
                    mma16816(acc[mt][np * 2 + 1], afr[mt], bfr[np][2], bfr[np][3]);
                }
            }
        }

        if (kt < NCHUNK - 1) {
            nbacc += b0.x*b0.x + b0.y*b0.y + b0.z*b0.z + b0.w*b0.w
                   + b1.x*b1.x + b1.y*b1.y + b1.z*b1.z + b1.w*b1.w;
            sbacc += b0.x + b0.y + b0.z + b0.w + b1.x + b1.y + b1.z + b1.w;
            uint4 pk;
            pk.x = packbf(b0.x, b0.y); pk.y = packbf(b0.z, b0.w);
            pk.z = packbf(b1.x, b1.y); pk.w = packbf(b1.z, b1.w);
            *(uint4*)(BbN + brow * STRB + bcg * 16) = pk;
            CP_WAIT0();
        }
        __syncthreads();
    }

    // ---- epilogue tables (overlay A0; safe after final sync) ----
    float* s_th  = (float*)(dsm + T_TH);
    float* s_na  = (float*)(dsm + T_NA);
    float* s_sa  = (float*)(dsm + T_SA);
    float* s_dap = (float*)(dsm + T_DAP);
    float* s_nb  = (float*)(dsm + T_NB);
    float* s_sb  = (float*)(dsm + T_SB);

    {
        float v = nbacc;
        v += __shfl_down_sync(0xffffffffu, v, 4);
        v += __shfl_down_sync(0xffffffffu, v, 2);
        v += __shfl_down_sync(0xffffffffu, v, 1);
        float u = sbacc;
        u += __shfl_down_sync(0xffffffffu, u, 4);
        u += __shfl_down_sync(0xffffffffu, u, 2);
        u += __shfl_down_sync(0xffffffffu, u, 1);
        if (bcg == 0) { s_nb[brow] = v; s_sb[brow] = u; }
    }
    if (tid < 256) {
        s_th[tid]  = g_thresh[tid];
        s_na[tid]  = g_na[tid];
        s_sa[tid]  = g_sa[tid];
        s_dap[tid] = g_dap[tid];
    }
    __syncthreads();

    const float cterm = (float)DIM * EPS_F * EPS_F;
    float sumtl = 0.f;
    int cnt = 0;
    #pragma unroll
    for (int mt = 0; mt < 2; mt++) {
        int i1 = i0w + mt * 16 + (lid >> 2);
        int i2 = i1 + 8;
        float th1 = s_th[i1], na1 = s_na[i1], sa1 = s_sa[i1], dp1 = s_dap[i1];
        float th2 = s_th[i2], na2 = s_na[i2], sa2 = s_sa[i2], dp2 = s_dap[i2];
        int g1 = i1 >> 5, g2 = i2 >> 5;
        unsigned bit1 = 1u << (i1 & 31), bit2 = 1u << (i2 & 31);
        #pragma unroll
        for (int nt = 0; nt < 4; nt++) {
            int jl = j0w + nt * 8 + (lid & 3) * 2;
            #pragma unroll
            for (int c = 0; c < 4; c++) {
                int jj = jl + (c & 1);
                float s = acc[mt][nt][c];
                float th  = (c < 2) ? th1 : th2;
                unsigned bit = (c < 2) ? bit1 : bit2;
                int g = (c < 2) ? g1 : g2;
                if (s > th && !(s_nn[jj * 8 + g] & bit)) {
                    float na = (c < 2) ? na1 : na2;
                    float sa = (c < 2) ? sa1 : sa2;
                    float dp = (c < 2) ? dp1 : dp2;
                    cnt++;
                    float dan2 = na + s_nb[jj] - 2.0f * s
                               + 2.0f * EPS_F * (sa - s_sb[jj]) + cterm;
                    float dan = sqrtf(fmaxf(dan2, 0.0f));
                    float tl = dp - dan + TMARGIN_F;
                    if (tl > 0.0f) sumtl += tl;
                }
            }
        }
    }
    sumtl = warpReduceSum(sumtl);
    cnt   = warpReduceSumI(cnt);
    if (lid == 0) { red_s[wid] = sumtl; red_c[wid] = cnt; }
    __syncthreads();
    if (tid == 0) {
        float ts = 0.f; int tc = 0;
        #pragma unroll
        for (int w = 0; w < 16; w++) { ts += red_s[w]; tc += red_c[w]; }
        if (tc > 0) { atomicAdd(&g_total, (double)ts); atomicAdd(&g_count, tc); }
        __threadfence();
        unsigned d = atomicAdd(&g_done, 1u);
        if (d == nblocks - 1) {
            g_done = 0;
            __threadfence();
            int c = g_count;
            out[0] = (c > 0) ? (float)(g_total / (double)c) : 0.0f;
        }
    }
}

extern "C" void kernel_launch(void* const* d_in, const int* in_sizes, int n_in,
                              void* d_out, int out_size) {
    const float* inputs_col  = (const float*)d_in[0];
    const float* inputs_row  = (const float*)d_in[1];
    const int*   targets_col = (const int*)d_in[2];
    const int*   targets_row = (const int*)d_in[3];
    const int*   qidxs       = (const int*)d_in[4];
    // d_in[5] = pidxs: dead in the reference loss
    const int*   nnegs       = (const int*)d_in[6];

    cudaFuncSetAttribute(gemm_kernel, cudaFuncAttributeMaxDynamicSharedMemorySize, SMEM_DYN);

    setup_kernel<<<BSZ, 128>>>(inputs_col, inputs_row, targets_col, qidxs, nnegs);
    gemm_kernel<<<MROW / BN, 512, SMEM_DYN>>>(inputs_row, targets_row,
                                              (float*)d_out, MROW / BN);
}

// round 6
// speedup vs baseline: 1.1060x; 1.1060x over previous
#include <cuda_runtime.h>
#include <cuda_bf16.h>
#include <math.h>
#include <float.h>
#include <stdint.h>

#define BSZ   256
#define MROW  32768
#define DIM   512
#define KNEG  10
#define MARGIN_F 0.1f
#define EPS_F 1e-6f
#define TMARGIN_F 0.31622776601683794f

#define BN 64             // j rows per CTA
#define BKC 64            // K per chunk (bf16)
#define NCHUNK (DIM / BKC)  // 8
#define PADK 72           // padded k-stride in bf16 elems (144 B)
#define STRB (PADK * 2)   // 144 bytes

// dynamic smem layout (bytes)
#define A_T0   0
#define A_T1   36864           // 256*144
#define B_T0   73728
#define B_T1   82944           // + 64*144
#define NN_OFF 92160           // 64*8 u32 = 2048
#define NNEG_OFF 94208         // 256*10 int = 10240
#define TROW_OFF 104448        // 64 int
#define SMEM_DYN 104704
// epilogue tables overlay the A0 buffer
#define T_TH  0
#define T_NA  1024
#define T_SA  2048
#define T_DAP 3072
#define T_NB  4096
#define T_SB  4352

// ---------------- scratch globals ----------------
__device__ float         g_thresh[BSZ];
__device__ float         g_na[BSZ];
__device__ float         g_sa[BSZ];
__device__ float         g_dap[BSZ];
__device__ int           g_nneg[BSZ * KNEG];
__device__ float         g_nb[MROW];
__device__ float         g_sb[MROW];
__device__ __align__(256) __nv_bfloat16 g_Abf[BSZ * DIM];
__device__ __align__(256) __nv_bfloat16 g_Bbf[(size_t)MROW * DIM];
__device__ double        g_total;
__device__ int           g_count;
__device__ unsigned      g_done = 0;

// ---------------- helpers ----------------
__device__ __forceinline__ uint32_t smem_u32(const void* p) {
    uint32_t a;
    asm("{ .reg .u64 t; cvta.to.shared.u64 t, %1; cvt.u32.u64 %0, t; }" : "=r"(a) : "l"(p));
    return a;
}
__device__ __forceinline__ void ldsm_x4(uint32_t* r, uint32_t addr) {
    asm volatile("ldmatrix.sync.aligned.m8n8.x4.shared.b16 {%0,%1,%2,%3}, [%4];"
                 : "=r"(r[0]), "=r"(r[1]), "=r"(r[2]), "=r"(r[3]) : "r"(addr));
}
__device__ __forceinline__ void mma16816(float* d, const uint32_t* a, uint32_t b0, uint32_t b1) {
    asm volatile(
        "mma.sync.aligned.m16n8k16.row.col.f32.bf16.bf16.f32 "
        "{%0,%1,%2,%3}, {%4,%5,%6,%7}, {%8,%9}, {%0,%1,%2,%3};"
        : "+f"(d[0]), "+f"(d[1]), "+f"(d[2]), "+f"(d[3])
        : "r"(a[0]), "r"(a[1]), "r"(a[2]), "r"(a[3]), "r"(b0), "r"(b1));
}
#define CP_ASYNC16(dst, src) \
    asm volatile("cp.async.cg.shared.global [%0], [%1], 16;" :: "r"(dst), "l"(src))
#define CP_COMMIT()  asm volatile("cp.async.commit_group;" ::: "memory")
#define CP_WAIT0()   asm volatile("cp.async.wait_group 0;" ::: "memory")

__inline__ __device__ float warpReduceSum(float v) {
    #pragma unroll
    for (int o = 16; o > 0; o >>= 1) v += __shfl_down_sync(0xffffffffu, v, o);
    return v;
}
__inline__ __device__ int warpReduceSumI(int v) {
    #pragma unroll
    for (int o = 16; o > 0; o >>= 1) v += __shfl_down_sync(0xffffffffu, v, o);
    return v;
}
__device__ __forceinline__ uint32_t packbf(float x, float y) {
    __nv_bfloat162 t = __float22bfloat162_rn(make_float2(x, y));
    return *(uint32_t*)&t;
}

// ---------------- Kernel A: per-query setup + A bf16 conversion ----------------
__global__ void setup_kernel(const float* __restrict__ col,
                             const float* __restrict__ row,
                             const int* __restrict__ targets_col,
                             const int* __restrict__ qidxs,
                             const int* __restrict__ nnegs) {
    int i = blockIdx.x;
    int tid = threadIdx.x;
    const float* q = col + (size_t)i * DIM;
    const float* p = row + (size_t)(BSZ + i) * DIM;

    float na = 0.f, sa = 0.f, ps = 0.f, dap2 = 0.f;
    for (int k = tid; k < DIM; k += blockDim.x) {
        float qv = q[k], pv = p[k];
        na += qv * qv;
        sa += qv;
        ps += qv * pv;
        float dlt = qv - pv + EPS_F;
        dap2 += dlt * dlt;
        g_Abf[i * DIM + k] = __float2bfloat16_rn(qv);
    }
    __shared__ float sh[4][4];
    int w = tid >> 5, l = tid & 31;
    na = warpReduceSum(na); sa = warpReduceSum(sa);
    ps = warpReduceSum(ps); dap2 = warpReduceSum(dap2);
    if (l == 0) { sh[0][w] = na; sh[1][w] = sa; sh[2][w] = ps; sh[3][w] = dap2; }
    __syncthreads();
    if (tid == 0) {
        na = 0.f; sa = 0.f; ps = 0.f; dap2 = 0.f;
        for (int k = 0; k < 4; k++) { na += sh[0][k]; sa += sh[1][k]; ps += sh[2][k]; dap2 += sh[3][k]; }
        int tc = targets_col[i];
        int qloc = 0, has = 0;
        for (int j = 0; j < BSZ; j++) if (qidxs[j] == tc) { qloc = j; has = 1; break; }
        g_thresh[i] = has ? (ps - MARGIN_F) : FLT_MAX;
        g_na[i] = na; g_sa[i] = sa; g_dap[i] = sqrtf(dap2);
        for (int k = 0; k < KNEG; k++) g_nneg[i * KNEG + k] = nnegs[qloc * KNEG + k];
        if (i == 0) { g_total = 0.0; g_count = 0; }
    }
}

// ---------------- Kernel B: convert inputs_row -> bf16 + row stats ----------------
// one warp per row; 8 warps per block
__global__ __launch_bounds__(256)
void convertB_kernel(const float* __restrict__ row) {
    int tid = threadIdx.x;
    int w = tid >> 5, lid = tid & 31;
    int j = blockIdx.x * 8 + w;
    const float4* src = (const float4*)(row + (size_t)j * DIM);
    uint2* dst = (uint2*)(g_Bbf + (size_t)j * DIM);

    float nb = 0.f, sb = 0.f;
    #pragma unroll
    for (int t = 0; t < 4; t++) {
        float4 v = src[lid + t * 32];
        nb += v.x*v.x + v.y*v.y + v.z*v.z + v.w*v.w;
        sb += v.x + v.y + v.z + v.w;
        uint2 pk;
        pk.x = packbf(v.x, v.y);
        pk.y = packbf(v.z, v.w);
        dst[lid + t * 32] = pk;
    }
    nb = warpReduceSum(nb);
    sb = warpReduceSum(sb);
    if (lid == 0) { g_nb[j] = nb; g_sb[j] = sb; }
}

// ---------------- Kernel C: gemm + mask + epilogue + finalize ----------------
__global__ __launch_bounds__(512, 2)
void gemm_kernel(const int* __restrict__ targets_row,
                 float* __restrict__ out, unsigned nblocks) {
    extern __shared__ char dsm[];
    __shared__ float red_s[16];
    __shared__ int   red_c[16];

    uint32_t sb = smem_u32(dsm);
    int tid = threadIdx.x;
    int wid = tid >> 5, lid = tid & 31;
    int j0 = blockIdx.x * BN;

    // warp tiling: 8 (i) x 2 (j); warp tile 32x32
    int i0w = (wid >> 1) * 32, j0w = (wid & 1) * 32;

    float acc[2][4][4];
    #pragma unroll
    for (int a = 0; a < 2; a++)
        #pragma unroll
        for (int b = 0; b < 4; b++)
            #pragma unroll
            for (int c = 0; c < 4; c++) acc[a][b][c] = 0.f;

    uint32_t a_lane = (uint32_t)((lid & 15) * STRB + (lid >> 4) * 16);
    uint32_t b_lane = (uint32_t)(((lid & 7) + ((lid >> 4) & 1) * 8) * STRB + ((lid >> 3) & 1) * 16);

    int*      s_nneg = (int*)(dsm + NNEG_OFF);
    int*      s_trow = (int*)(dsm + TROW_OFF);
    unsigned* s_nn   = (unsigned*)(dsm + NN_OFF);

    // A loader: 4 granules/thread; B loader: 1 granule/thread
    int arow = tid >> 3, ah = tid & 7;            // A: rows tid>>3 + p*64, col granule tid&7
    const char* Asrc = (const char*)(g_Abf + arow * DIM + ah * 8);
    const char* Bsrc = (const char*)(g_Bbf + (size_t)(j0 + arow) * DIM + ah * 8);
    uint32_t a_sdst = (uint32_t)(arow * STRB + ah * 16);

    // ---- prologue ----
    {
        #pragma unroll
        for (int p = 0; p < 5; p++) s_nneg[tid + p * 512] = g_nneg[tid + p * 512];
        if (tid < BN) s_trow[tid] = targets_row[j0 + tid];

        #pragma unroll
        for (int p = 0; p < 4; p++)
            CP_ASYNC16(sb + A_T0 + a_sdst + p * 64 * STRB, Asrc + (size_t)p * 64 * DIM * 2);
        CP_ASYNC16(sb + B_T0 + a_sdst, Bsrc);
        CP_COMMIT();
        __syncthreads();   // staging visible

        // mask compute: warp handles 8 groups x 4 rows
        {
            int myneg[KNEG];
            #pragma unroll 1
            for (int g = 0; g < 8; g++) {
                int i = g * 32 + lid;
                #pragma unroll
                for (int k = 0; k < KNEG; k++) myneg[k] = s_nneg[i * KNEG + k];
                #pragma unroll
                for (int r = 0; r < 4; r++) {
                    int rrow = wid * 4 + r;
                    int t = s_trow[rrow];
                    bool m = false;
                    #pragma unroll
                    for (int k = 0; k < KNEG; k++) m = m || (myneg[k] == t);
                    unsigned word = __ballot_sync(0xffffffffu, m);
                    if (lid == 0) s_nn[rrow * 8 + g] = word;
                }
            }
        }
        CP_WAIT0();
        __syncthreads();
    }

    // ---- mainloop ----
    #pragma unroll 1
    for (int kt = 0; kt < NCHUNK; kt++) {
        int buf = kt & 1;
        uint32_t Ab = sb + (buf ? A_T1 : A_T0);
        uint32_t Bb = sb + (buf ? B_T1 : B_T0);

        if (kt < NCHUNK - 1) {
            uint32_t AbN = sb + (buf ? A_T0 : A_T1);
            uint32_t BbN = sb + (buf ? B_T0 : B_T1);
            size_t kc = (size_t)(kt + 1) * BKC * 2;   // byte offset in row
            #pragma unroll
            for (int p = 0; p < 4; p++)
                CP_ASYNC16(AbN + a_sdst + p * 64 * STRB, Asrc + (size_t)p * 64 * DIM * 2 + kc);
            CP_ASYNC16(BbN + a_sdst, Bsrc + kc);
            CP_COMMIT();
        }

        #pragma unroll
        for (int ks = 0; ks < BKC; ks += 16) {
            uint32_t afr[2][4], bfr[2][4];
            #pragma unroll
            for (int mt = 0; mt < 2; mt++)
                ldsm_x4(afr[mt], Ab + (uint32_t)((i0w + mt * 16) * STRB + ks * 2) + a_lane);
            #pragma unroll
            for (int np = 0; np < 2; np++)
                ldsm_x4(bfr[np], Bb + (uint32_t)((j0w + np * 16) * STRB + ks * 2) + b_lane);
            #pragma unroll
            for (int mt = 0; mt < 2; mt++) {
                #pragma unroll
                for (int np = 0; np < 2; np++) {
                    mma16816(acc[mt][np * 2 + 0], afr[mt], bfr[np][0], bfr[np][1]);
                    mma16816(acc[mt][np * 2 + 1], afr[mt], bfr[np][2], bfr[np][3]);
                }
            }
        }

        if (kt < NCHUNK - 1) CP_WAIT0();
        __syncthreads();
    }

    // ---- epilogue tables (overlay A0; safe after final sync) ----
    float* s_th  = (float*)(dsm + T_TH);
    float* s_na  = (float*)(dsm + T_NA);
    float* s_sa  = (float*)(dsm + T_SA);
    float* s_dap = (float*)(dsm + T_DAP);
    float* s_nb  = (float*)(dsm + T_NB);
    float* s_sb  = (float*)(dsm + T_SB);

    if (tid < 256) {
        s_th[tid]  = g_thresh[tid];
        s_na[tid]  = g_na[tid];
        s_sa[tid]  = g_sa[tid];
        s_dap[tid] = g_dap[tid];
    }
    if (tid < BN) {
        s_nb[tid] = g_nb[j0 + tid];
        s_sb[tid] = g_sb[j0 + tid];
    }
    __syncthreads();

    const float cterm = (float)DIM * EPS_F * EPS_F;
    float sumtl = 0.f;
    int cnt = 0;
    #pragma unroll
    for (int mt = 0; mt < 2; mt++) {
        int i1 = i0w + mt * 16 + (lid >> 2);
        int i2 = i1 + 8;
        float th1 = s_th[i1], na1 = s_na[i1], sa1 = s_sa[i1], dp1 = s_dap[i1];
        float th2 = s_th[i2], na2 = s_na[i2], sa2 = s_sa[i2], dp2 = s_dap[i2];
        int g1 = i1 >> 5, g2 = i2 >> 5;
        unsigned bit1 = 1u << (i1 & 31), bit2 = 1u << (i2 & 31);
        #pragma unroll
        for (int nt = 0; nt < 4; nt++) {
            int jl = j0w + nt * 8 + (lid & 3) * 2;
            #pragma unroll
            for (int c = 0; c < 4; c++) {
                int jj = jl + (c & 1);
                float s = acc[mt][nt][c];
                float th  = (c < 2) ? th1 : th2;
                unsigned bit = (c < 2) ? bit1 : bit2;
                int g = (c < 2) ? g1 : g2;
                if (s > th && !(s_nn[jj * 8 + g] & bit)) {
                    float na = (c < 2) ? na1 : na2;
                    float sa = (c < 2) ? sa1 : sa2;
                    float dp = (c < 2) ? dp1 : dp2;
                    cnt++;
                    float dan2 = na + s_nb[jj] - 2.0f * s
                               + 2.0f * EPS_F * (sa - s_sb[jj]) + cterm;
                    float dan = sqrtf(fmaxf(dan2, 0.0f));
                    float tl = dp - dan + TMARGIN_F;
                    if (tl > 0.0f) sumtl += tl;
                }
            }
        }
    }
    sumtl = warpReduceSum(sumtl);
    cnt   = warpReduceSumI(cnt);
    if (lid == 0) { red_s[wid] = sumtl; red_c[wid] = cnt; }
    __syncthreads();
    if (tid == 0) {
        float ts = 0.f; int tc = 0;
        #pragma unroll
        for (int w = 0; w < 16; w++) { ts += red_s[w]; tc += red_c[w]; }
        if (tc > 0) { atomicAdd(&g_total, (double)ts); atomicAdd(&g_count, tc); }
        __threadfence();
        unsigned d = atomicAdd(&g_done, 1u);
        if (d == nblocks - 1) {
            g_done = 0;
            __threadfence();
            int c = g_count;
            out[0] = (c > 0) ? (float)(g_total / (double)c) : 0.0f;
        }
    }
}

extern "C" void kernel_launch(void* const* d_in, const int* in_sizes, int n_in,
                              void* d_out, int out_size) {
    const float* inputs_col  = (const float*)d_in[0];
    const float* inputs_row  = (const float*)d_in[1];
    const int*   targets_col = (const int*)d_in[2];
    const int*   targets_row = (const int*)d_in[3];
    const int*   qidxs       = (const int*)d_in[4];
    // d_in[5] = pidxs: dead in the reference loss
    const int*   nnegs       = (const int*)d_in[6];

    cudaFuncSetAttribute(gemm_kernel, cudaFuncAttributeMaxDynamicSharedMemorySize, SMEM_DYN);

    setup_kernel<<<BSZ, 128>>>(inputs_col, inputs_row, targets_col, qidxs, nnegs);
    convertB_kernel<<<MROW / 8, 256>>>(inputs_row);
    gemm_kernel<<<MROW / BN, 512, SMEM_DYN>>>(targets_row, (float*)d_out, MROW / BN);
}

// round 7
// speedup vs baseline: 1.3272x; 1.2000x over previous
#include <cuda_runtime.h>
#include <cuda_bf16.h>
#include <math.h>
#include <float.h>
#include <stdint.h>

#define BSZ   256
#define MROW  32768
#define DIM   512
#define KNEG  10
#define MARGIN_F 0.1f
#define EPS_F 1e-6f
#define TMARGIN_F 0.31622776601683794f

#define BN 64             // j rows per CTA
#define BKC 64            // K per chunk (bf16)
#define NCHUNK (DIM / BKC)  // 8
#define PADK 72           // padded k-stride in bf16 elems (144 B)
#define STRB (PADK * 2)   // 144 bytes

// dynamic smem layout (bytes)
#define A_T0   0
#define A_T1   36864           // 256*144
#define B_T0   73728
#define B_T1   82944           // + 64*144
#define NN_OFF 92160           // 64*8 u32 = 2048
#define NNEG_OFF 94208         // 256*10 int = 10240
#define TROW_OFF 104448        // 64 int
#define SMEM_DYN 104704
// epilogue tables overlay the A0 buffer
#define T_TH  0
#define T_NA  1024
#define T_SA  2048
#define T_DAP 3072
#define T_NB  4096
#define T_SB  4352

#define CONV_BLOCKS (MROW / 8)      // 4096

// ---------------- scratch globals ----------------
__device__ float         g_thresh[BSZ];
__device__ float         g_na[BSZ];
__device__ float         g_sa[BSZ];
__device__ float         g_dap[BSZ];
__device__ int           g_nneg[BSZ * KNEG];
__device__ float         g_nb[MROW];
__device__ float         g_sb[MROW];
__device__ __align__(256) __nv_bfloat16 g_Abf[BSZ * DIM];
__device__ __align__(256) __nv_bfloat16 g_Bbf[(size_t)MROW * DIM];
__device__ double        g_total;
__device__ int           g_count;
__device__ unsigned      g_done = 0;

// ---------------- helpers ----------------
__device__ __forceinline__ uint32_t smem_u32(const void* p) {
    uint32_t a;
    asm("{ .reg .u64 t; cvta.to.shared.u64 t, %1; cvt.u32.u64 %0, t; }" : "=r"(a) : "l"(p));
    return a;
}
__device__ __forceinline__ void ldsm_x4(uint32_t* r, uint32_t addr) {
    asm volatile("ldmatrix.sync.aligned.m8n8.x4.shared.b16 {%0,%1,%2,%3}, [%4];"
                 : "=r"(r[0]), "=r"(r[1]), "=r"(r[2]), "=r"(r[3]) : "r"(addr));
}
__device__ __forceinline__ void mma16816(float* d, const uint32_t* a, uint32_t b0, uint32_t b1) {
    asm volatile(
        "mma.sync.aligned.m16n8k16.row.col.f32.bf16.bf16.f32 "
        "{%0,%1,%2,%3}, {%4,%5,%6,%7}, {%8,%9}, {%0,%1,%2,%3};"
        : "+f"(d[0]), "+f"(d[1]), "+f"(d[2]), "+f"(d[3])
        : "r"(a[0]), "r"(a[1]), "r"(a[2]), "r"(a[3]), "r"(b0), "r"(b1));
}
#define CP_ASYNC16(dst, src) \
    asm volatile("cp.async.cg.shared.global [%0], [%1], 16;" :: "r"(dst), "l"(src))
#define CP_COMMIT()  asm volatile("cp.async.commit_group;" ::: "memory")
#define CP_WAIT0()   asm volatile("cp.async.wait_group 0;" ::: "memory")

__inline__ __device__ float warpReduceSum(float v) {
    #pragma unroll
    for (int o = 16; o > 0; o >>= 1) v += __shfl_down_sync(0xffffffffu, v, o);
    return v;
}
__inline__ __device__ int warpReduceSumI(int v) {
    #pragma unroll
    for (int o = 16; o > 0; o >>= 1) v += __shfl_down_sync(0xffffffffu, v, o);
    return v;
}
__device__ __forceinline__ uint32_t packbf(float x, float y) {
    __nv_bfloat162 t = __float22bfloat162_rn(make_float2(x, y));
    return *(uint32_t*)&t;
}

// ---------------- Kernel A: prep = B convert (+stats) AND per-query setup ----------------
// blocks [0, CONV_BLOCKS): convert 8 rows of inputs_row to bf16, fuse nb/sb
// blocks [CONV_BLOCKS, CONV_BLOCKS+BSZ): per-query setup for i = bid - CONV_BLOCKS
__global__ __launch_bounds__(256)
void prep_kernel(const float* __restrict__ col,
                 const float* __restrict__ row,
                 const int* __restrict__ targets_col,
                 const int* __restrict__ qidxs,
                 const int* __restrict__ nnegs) {
    int bid = blockIdx.x;
    int tid = threadIdx.x;
    int w = tid >> 5, lid = tid & 31;

    if (bid < CONV_BLOCKS) {
        // ---- convert part: one warp per row ----
        int j = bid * 8 + w;
        const float4* src = (const float4*)(row + (size_t)j * DIM);
        uint2* dst = (uint2*)(g_Bbf + (size_t)j * DIM);
        float nb = 0.f, sb = 0.f;
        #pragma unroll
        for (int t = 0; t < 4; t++) {
            float4 v = src[lid + t * 32];
            nb += v.x*v.x + v.y*v.y + v.z*v.z + v.w*v.w;
            sb += v.x + v.y + v.z + v.w;
            uint2 pk;
            pk.x = packbf(v.x, v.y);
            pk.y = packbf(v.z, v.w);
            dst[lid + t * 32] = pk;
        }
        nb = warpReduceSum(nb);
        sb = warpReduceSum(sb);
        if (lid == 0) { g_nb[j] = nb; g_sb[j] = sb; }
        return;
    }

    // ---- setup part: one block per query i ----
    int i = bid - CONV_BLOCKS;
    const float* q = col + (size_t)i * DIM;
    const float* p = row + (size_t)(BSZ + i) * DIM;

    float na = 0.f, sa = 0.f, ps = 0.f, dap2 = 0.f;
    #pragma unroll
    for (int t = 0; t < 2; t++) {
        int k = tid + t * 256;
        float qv = q[k], pv = p[k];
        na += qv * qv;
        sa += qv;
        ps += qv * pv;
        float dlt = qv - pv + EPS_F;
        dap2 += dlt * dlt;
        g_Abf[i * DIM + k] = __float2bfloat16_rn(qv);
    }
    __shared__ float sh[4][8];
    na = warpReduceSum(na); sa = warpReduceSum(sa);
    ps = warpReduceSum(ps); dap2 = warpReduceSum(dap2);
    if (lid == 0) { sh[0][w] = na; sh[1][w] = sa; sh[2][w] = ps; sh[3][w] = dap2; }
    __syncthreads();

    if (w == 0) {
        // warp-parallel search for qloc: 8 ballot rounds over 256 entries
        int tc = targets_col[i];
        int qloc = 0, has = 0;
        #pragma unroll
        for (int g = 0; g < 8; g++) {
            int qv = qidxs[g * 32 + lid];
            unsigned word = __ballot_sync(0xffffffffu, qv == tc);
            if (!has && word) { qloc = g * 32 + __ffs(word) - 1; has = 1; }
        }
        // lane-parallel nneg gather (10 lanes)
        if (lid < KNEG) g_nneg[i * KNEG + lid] = nnegs[qloc * KNEG + lid];
        if (lid == 0) {
            float rna = 0.f, rsa = 0.f, rps = 0.f, rdap2 = 0.f;
            #pragma unroll
            for (int k = 0; k < 8; k++) {
                rna += sh[0][k]; rsa += sh[1][k]; rps += sh[2][k]; rdap2 += sh[3][k];
            }
            g_thresh[i] = has ? (rps - MARGIN_F) : FLT_MAX;
            g_na[i] = rna; g_sa[i] = rsa; g_dap[i] = sqrtf(rdap2);
            if (i == 0) { g_total = 0.0; g_count = 0; }
        }
    }
}

// ---------------- Kernel B: gemm + mask + epilogue + finalize ----------------
__global__ __launch_bounds__(512, 2)
void gemm_kernel(const int* __restrict__ targets_row,
                 float* __restrict__ out, unsigned nblocks) {
    extern __shared__ char dsm[];
    __shared__ float red_s[16];
    __shared__ int   red_c[16];

    uint32_t sb = smem_u32(dsm);
    int tid = threadIdx.x;
    int wid = tid >> 5, lid = tid & 31;
    int j0 = blockIdx.x * BN;

    // warp tiling: 8 (i) x 2 (j); warp tile 32x32
    int i0w = (wid >> 1) * 32, j0w = (wid & 1) * 32;

    float acc[2][4][4];
    #pragma unroll
    for (int a = 0; a < 2; a++)
        #pragma unroll
        for (int b = 0; b < 4; b++)
            #pragma unroll
            for (int c = 0; c < 4; c++) acc[a][b][c] = 0.f;

    uint32_t a_lane = (uint32_t)((lid & 15) * STRB + (lid >> 4) * 16);
    uint32_t b_lane = (uint32_t)(((lid & 7) + ((lid >> 4) & 1) * 8) * STRB + ((lid >> 3) & 1) * 16);

    int*      s_nneg = (int*)(dsm + NNEG_OFF);
    int*      s_trow = (int*)(dsm + TROW_OFF);
    unsigned* s_nn   = (unsigned*)(dsm + NN_OFF);

    // A loader: 4 granules/thread; B loader: 1 granule/thread
    int arow = tid >> 3, ah = tid & 7;
    const char* Asrc = (const char*)(g_Abf + arow * DIM + ah * 8);
    const char* Bsrc = (const char*)(g_Bbf + (size_t)(j0 + arow) * DIM + ah * 8);
    uint32_t a_sdst = (uint32_t)(arow * STRB + ah * 16);

    // ---- prologue ----
    {
        #pragma unroll
        for (int p = 0; p < 5; p++) s_nneg[tid + p * 512] = g_nneg[tid + p * 512];
        if (tid < BN) s_trow[tid] = targets_row[j0 + tid];

        #pragma unroll
        for (int p = 0; p < 4; p++)
            CP_ASYNC16(sb + A_T0 + a_sdst + p * 64 * STRB, Asrc + (size_t)p * 64 * DIM * 2);
        CP_ASYNC16(sb + B_T0 + a_sdst, Bsrc);
        CP_COMMIT();
        __syncthreads();   // staging visible

        // mask compute: warp handles 8 groups x 4 rows
        {
            int myneg[KNEG];
            #pragma unroll 1
            for (int g = 0; g < 8; g++) {
                int i = g * 32 + lid;
                #pragma unroll
                for (int k = 0; k < KNEG; k++) myneg[k] = s_nneg[i * KNEG + k];
                #pragma unroll
                for (int r = 0; r < 4; r++) {
                    int rrow = wid * 4 + r;
                    int t = s_trow[rrow];
                    bool m = false;
                    #pragma unroll
                    for (int k = 0; k < KNEG; k++) m = m || (myneg[k] == t);
                    unsigned word = __ballot_sync(0xffffffffu, m);
                    if (lid == 0) s_nn[rrow * 8 + g] = word;
                }
            }
        }
        CP_WAIT0();
        __syncthreads();
    }

    // ---- mainloop ----
    #pragma unroll 1
    for (int kt = 0; kt < NCHUNK; kt++) {
        int buf = kt & 1;
        uint32_t Ab = sb + (buf ? A_T1 : A_T0);
        uint32_t Bb = sb + (buf ? B_T1 : B_T0);

        if (kt < NCHUNK - 1) {
            uint32_t AbN = sb + (buf ? A_T0 : A_T1);
            uint32_t BbN = sb + (buf ? B_T0 : B_T1);
            size_t kc = (size_t)(kt + 1) * BKC * 2;   // byte offset in row
            #pragma unroll
            for (int p = 0; p < 4; p++)
                CP_ASYNC16(AbN + a_sdst + p * 64 * STRB, Asrc + (size_t)p * 64 * DIM * 2 + kc);
            CP_ASYNC16(BbN + a_sdst, Bsrc + kc);
            CP_COMMIT();
        }

        #pragma unroll
        for (int ks = 0; ks < BKC; ks += 16) {
            uint32_t afr[2][4], bfr[2][4];
            #pragma unroll
            for (int mt = 0; mt < 2; mt++)
                ldsm_x4(afr[mt], Ab + (uint32_t)((i0w + mt * 16) * STRB + ks * 2) + a_lane);
            #pragma unroll
            for (int np = 0; np < 2; np++)
                ldsm_x4(bfr[np], Bb + (uint32_t)((j0w + np * 16) * STRB + ks * 2) + b_lane);
            #pragma unroll
            for (int mt = 0; mt < 2; mt++) {
                #pragma unroll
                for (int np = 0; np < 2; np++) {
                    mma16816(acc[mt][np * 2 + 0], afr[mt], bfr[np][0], bfr[np][1]);
                    mma16816(acc[mt][np * 2 + 1], afr[mt], bfr[np][2], bfr[np][3]);
                }
            }
        }

        if (kt < NCHUNK - 1) CP_WAIT0();
        __syncthreads();
    }

    // ---- epilogue tables (overlay A0; safe after final sync) ----
    float* s_th  = (float*)(dsm + T_TH);
    float* s_na  = (float*)(dsm + T_NA);
    float* s_sa  = (float*)(dsm + T_SA);
    float* s_dap = (float*)(dsm + T_DAP);
    float* s_nb  = (float*)(dsm + T_NB);
    float* s_sb  = (float*)(dsm + T_SB);

    if (tid < 256) {
        s_th[tid]  = g_thresh[tid];
        s_na[tid]  = g_na[tid];
        s_sa[tid]  = g_sa[tid];
        s_dap[tid] = g_dap[tid];
    }
    if (tid < BN) {
        s_nb[tid] = g_nb[j0 + tid];
        s_sb[tid] = g_sb[j0 + tid];
    }
    __syncthreads();

    const float cterm = (float)DIM * EPS_F * EPS_F;
    float sumtl = 0.f;
    int cnt = 0;
    #pragma unroll
    for (int mt = 0; mt < 2; mt++) {
        int i1 = i0w + mt * 16 + (lid >> 2);
        int i2 = i1 + 8;
        float th1 = s_th[i1], na1 = s_na[i1], sa1 = s_sa[i1], dp1 = s_dap[i1];
        float th2 = s_th[i2], na2 = s_na[i2], sa2 = s_sa[i2], dp2 = s_dap[i2];
        int g1 = i1 >> 5, g2 = i2 >> 5;
        unsigned bit1 = 1u << (i1 & 31), bit2 = 1u << (i2 & 31);
        #pragma unroll
        for (int nt = 0; nt < 4; nt++) {
            int jl = j0w + nt * 8 + (lid & 3) * 2;
            #pragma unroll
            for (int c = 0; c < 4; c++) {
                int jj = jl + (c & 1);
                float s = acc[mt][nt][c];
                float th  = (c < 2) ? th1 : th2;
                unsigned bit = (c < 2) ? bit1 : bit2;
                int g = (c < 2) ? g1 : g2;
                if (s > th && !(s_nn[jj * 8 + g] & bit)) {
                    float na = (c < 2) ? na1 : na2;
                    float sa = (c < 2) ? sa1 : sa2;
                    float dp = (c < 2) ? dp1 : dp2;
                    cnt++;
                    float dan2 = na + s_nb[jj] - 2.0f * s
                               + 2.0f * EPS_F * (sa - s_sb[jj]) + cterm;
                    float dan = sqrtf(fmaxf(dan2, 0.0f));
                    float tl = dp - dan + TMARGIN_F;
                    if (tl > 0.0f) sumtl += tl;
                }
            }
        }
    }
    sumtl = warpReduceSum(sumtl);
    cnt   = warpReduceSumI(cnt);
    if (lid == 0) { red_s[wid] = sumtl; red_c[wid] = cnt; }
    __syncthreads();
    if (tid == 0) {
        float ts = 0.f; int tc = 0;
        #pragma unroll
        for (int w = 0; w < 16; w++) { ts += red_s[w]; tc += red_c[w]; }
        if (tc > 0) { atomicAdd(&g_total, (double)ts); atomicAdd(&g_count, tc); }
        __threadfence();
        unsigned d = atomicAdd(&g_done, 1u);
        if (d == nblocks - 1) {
            g_done = 0;
            __threadfence();
            int c = g_count;
            out[0] = (c > 0) ? (float)(g_total / (double)c) : 0.0f;
        }
    }
}

extern "C" void kernel_launch(void* const* d_in, const int* in_sizes, int n_in,
                              void* d_out, int out_size) {
    const float* inputs_col  = (const float*)d_in[0];
    const float* inputs_row  = (const float*)d_in[1];
    const int*   targets_col = (const int*)d_in[2];
    const int*   targets_row = (const int*)d_in[3];
    const int*   qidxs       = (const int*)d_in[4];
    // d_in[5] = pidxs: dead in the reference loss
    const int*   nnegs       = (const int*)d_in[6];

    cudaFuncSetAttribute(gemm_kernel, cudaFuncAttributeMaxDynamicSharedMemorySize, SMEM_DYN);

    prep_kernel<<<CONV_BLOCKS + BSZ, 256>>>(inputs_col, inputs_row, targets_col,
                                            qidxs, nnegs);
    gemm_kernel<<<MROW / BN, 512, SMEM_DYN>>>(targets_row, (float*)d_out, MROW / BN);
}